// round 14
// baseline (speedup 1.0000x reference)
#include <cuda_runtime.h>
#include <cuda_bf16.h>
#include <cstdint>

#define N0      4096
#define NUM     8192
#define DD      512
#define KSP     1536          // split K: [h | h | l] vs [h | l | h]
#define CLASSES 100
#define NCH     24            // 1536 / 64
#define STAGE_BYTES 32768     // 16KB A + 16KB B
#define GEMM_SMEM 67712       // max(2 stages 64KB, 128x132 f32 stage 67.6KB)
#define NBLK    256           // 32-col blocks per row
#define NTRI    2080          // 2016 strict-lower + 64 diagonal

// ---- device scratch ----
__device__ float g_x2[(size_t)NUM * DD];
__device__ float g_bb[NUM];
__device__ float g_y2[NUM];
__device__ float g_S[(size_t)NUM * NUM];
__device__ float g_BM[(size_t)NUM * NBLK];          // per-32-col block minima
__device__ __nv_bfloat16 g_A2[(size_t)NUM * KSP];   // split(-2*x2)
__device__ __nv_bfloat16 g_B2[(size_t)NUM * KSP];   // split(x2)
__device__ float g_musum[CLASSES * DD];
__device__ float g_cnt[CLASSES];
__device__ float g_mu[CLASSES * DD];
__device__ float g_mumu[CLASSES];
__device__ float g_ptgm[NUM];
__device__ float g_ptknn[NUM];

__device__ __forceinline__ uint32_t smem_u32(const void* p) {
    uint32_t a;
    asm("{ .reg .u64 t; cvta.to.shared.u64 t, %1; cvt.u32.u64 %0, t; }" : "=r"(a) : "l"(p));
    return a;
}
__device__ __forceinline__ void cp16(uint32_t dst, const void* src) {
    asm volatile("cp.async.cg.shared.global [%0], [%1], 16;" :: "r"(dst), "l"(src));
}
__device__ __forceinline__ void ldm_x4(uint32_t addr, uint32_t& d0, uint32_t& d1,
                                       uint32_t& d2, uint32_t& d3) {
    asm volatile("ldmatrix.sync.aligned.m8n8.x4.shared.b16 {%0,%1,%2,%3}, [%4];"
                 : "=r"(d0), "=r"(d1), "=r"(d2), "=r"(d3) : "r"(addr));
}
__device__ __forceinline__ void mma_bf16(float* c, const uint32_t* a, uint32_t b0, uint32_t b1) {
    asm volatile("mma.sync.aligned.m16n8k16.row.col.f32.bf16.bf16.f32 "
                 "{%0,%1,%2,%3},{%4,%5,%6,%7},{%8,%9},{%0,%1,%2,%3};"
                 : "+f"(c[0]), "+f"(c[1]), "+f"(c[2]), "+f"(c[3])
                 : "r"(a[0]), "r"(a[1]), "r"(a[2]), "r"(a[3]), "r"(b0), "r"(b1));
}
__device__ __forceinline__ uint32_t pk(__nv_bfloat16 a, __nv_bfloat16 b) {
    union { __nv_bfloat162 h; uint32_t u; } t;
    t.h = __nv_bfloat162(a, b);
    return t.u;
}

// ---------------------------------------------------------------
// build: x2, bb, y lower half, and bf16 split operands (packed stores)
// ---------------------------------------------------------------
__global__ void build_kernel(const float* __restrict__ x, const float* __restrict__ y,
                             const float* __restrict__ lamp, const int* __restrict__ perm) {
    int row = blockIdx.x;
    int tid = threadIdx.x;
    float4 v;
    if (row < N0) {
        v = ((const float4*)(x + (size_t)row * DD))[tid];
        if (tid == 0) g_y2[row] = y[row];
    } else {
        int j = row - N0;
        float lam = *lamp, oml = 1.f - lam;
        int p = perm[j];
        float4 va = ((const float4*)(x + (size_t)j * DD))[tid];
        float4 vb = ((const float4*)(x + (size_t)p * DD))[tid];
        v.x = va.x * lam + vb.x * oml;
        v.y = va.y * lam + vb.y * oml;
        v.z = va.z * lam + vb.z * oml;
        v.w = va.w * lam + vb.w * oml;
    }
    ((float4*)(g_x2 + (size_t)row * DD))[tid] = v;
    float ss = v.x * v.x + v.y * v.y + v.z * v.z + v.w * v.w;

    float f[4] = {v.x, v.y, v.z, v.w};
    __nv_bfloat16* A = g_A2 + (size_t)row * KSP;
    __nv_bfloat16* B = g_B2 + (size_t)row * KSP;
    #pragma unroll
    for (int e = 0; e < 4; e += 2) {
        int d = tid * 4 + e;
        __nv_bfloat16 hb0, lb0, ha0, la0, hb1, lb1, ha1, la1;
        {
            float fb = f[e];
            hb0 = __float2bfloat16(fb);
            lb0 = __float2bfloat16(fb - __bfloat162float(hb0));
            float fa = -2.f * fb;
            ha0 = __float2bfloat16(fa);
            la0 = __float2bfloat16(fa - __bfloat162float(ha0));
        }
        {
            float fb = f[e + 1];
            hb1 = __float2bfloat16(fb);
            lb1 = __float2bfloat16(fb - __bfloat162float(hb1));
            float fa = -2.f * fb;
            ha1 = __float2bfloat16(fa);
            la1 = __float2bfloat16(fa - __bfloat162float(ha1));
        }
        *(uint32_t*)(A + d)        = pk(ha0, ha1);
        *(uint32_t*)(A + d + 512)  = pk(ha0, ha1);
        *(uint32_t*)(A + d + 1024) = pk(la0, la1);
        *(uint32_t*)(B + d)        = pk(hb0, hb1);
        *(uint32_t*)(B + d + 512)  = pk(lb0, lb1);
        *(uint32_t*)(B + d + 1024) = pk(hb0, hb1);
    }

    __shared__ float red[128];
    red[tid] = ss;
    __syncthreads();
    #pragma unroll
    for (int s = 64; s > 0; s >>= 1) {
        if (tid < s) red[tid] += red[tid + s];
        __syncthreads();
    }
    if (tid == 0) g_bb[row] = red[0];
}

// ---------------------------------------------------------------
// mma.sync distance GEMM, compact triangular grid (diagonal tiles LAST),
// mirror + 32-col block minima.
// CTA 128x128, 8 warps (2x4), warp tile 64x32, BK=64, 2-stage cp.async
// ---------------------------------------------------------------
__global__ __launch_bounds__(256, 2) void gemm_mma() {
    int b = blockIdx.x;
    int by, bx;
    if (b < 2016) {            // strict lower triangle: idx = by*(by-1)/2 + bx, bx < by
        by = (int)((1.f + sqrtf(8.f * (float)b + 1.f)) * 0.5f);
        while (by * (by - 1) / 2 > b) by--;
        while ((by + 1) * by / 2 <= b) by++;
        bx = b - by * (by - 1) / 2;
    } else {                   // diagonal tiles last (light: no mirror)
        by = bx = b - 2016;
    }

    extern __shared__ char smem[];
    const int tid  = threadIdx.x;
    const int lane = tid & 31;
    const int w    = tid >> 5;
    const int wm   = w >> 2, wn = w & 3;
    const uint32_t sbase = smem_u32(smem);

    const char* gA = (const char*)(g_A2 + (size_t)(by * 128) * KSP);
    const char* gB = (const char*)(g_B2 + (size_t)(bx * 128) * KSP);

    const int lrow = tid >> 3;   // 0..31
    const int lseg = tid & 7;

    float acc[4][4][4];
    #pragma unroll
    for (int mt = 0; mt < 4; mt++)
        #pragma unroll
        for (int nt = 0; nt < 4; nt++)
            #pragma unroll
            for (int e = 0; e < 4; e++) acc[mt][nt][e] = 0.f;

    #define ISSUE(chunk, stg)                                                        \
    {                                                                                \
        uint32_t sA = sbase + (stg) * STAGE_BYTES;                                   \
        uint32_t sB = sA + 16384;                                                    \
        _Pragma("unroll")                                                            \
        for (int r = 0; r < 4; r++) {                                                \
            int row = lrow + r * 32;                                                 \
            uint32_t d = (uint32_t)(row * 128 + ((lseg ^ (row & 7)) * 16));          \
            cp16(sA + d, gA + (size_t)row * (KSP * 2) + (chunk) * 128 + lseg * 16);  \
            cp16(sB + d, gB + (size_t)row * (KSP * 2) + (chunk) * 128 + lseg * 16);  \
        }                                                                            \
        asm volatile("cp.async.commit_group;" ::: "memory");                         \
    }

    ISSUE(0, 0);
    for (int i = 0; i < NCH; i++) {
        const int stg = i & 1;
        if (i + 1 < NCH) {
            ISSUE(i + 1, stg ^ 1);
            asm volatile("cp.async.wait_group 1;" ::: "memory");
        } else {
            asm volatile("cp.async.wait_group 0;" ::: "memory");
        }
        __syncthreads();

        const uint32_t sA = sbase + stg * STAGE_BYTES;
        const uint32_t sB = sA + 16384;
        #pragma unroll
        for (int kk = 0; kk < 4; kk++) {
            const int half = lane >> 4;
            uint32_t a[4][4];
            #pragma unroll
            for (int mt = 0; mt < 4; mt++) {
                int row = wm * 64 + mt * 16 + (lane & 15);
                uint32_t ad = sA + row * 128 + (((kk * 2 + half) ^ (row & 7)) * 16);
                ldm_x4(ad, a[mt][0], a[mt][1], a[mt][2], a[mt][3]);
            }
            uint32_t bfr[2][4];
            #pragma unroll
            for (int pt = 0; pt < 2; pt++) {
                int nrow = wn * 32 + pt * 16 + ((lane >> 3) & 1) * 8 + (lane & 7);
                uint32_t bd = sB + nrow * 128 + (((kk * 2 + half) ^ (nrow & 7)) * 16);
                ldm_x4(bd, bfr[pt][0], bfr[pt][1], bfr[pt][2], bfr[pt][3]);
            }
            #pragma unroll
            for (int mt = 0; mt < 4; mt++)
                #pragma unroll
                for (int nt = 0; nt < 4; nt++) {
                    int pt = nt >> 1, sub = nt & 1;
                    mma_bf16(acc[mt][nt], a[mt], bfr[pt][sub], bfr[pt][sub + 2]);
                }
        }
        __syncthreads();
    }
    #undef ISSUE

    const int mb0 = by * 128, nb0 = bx * 128;
    const int r0 = lane >> 2;
    const int c0 = (lane & 3) * 2;

    // ---- straight tile + 32-col block minima ----
    {
        float bbv[4][2];
        #pragma unroll
        for (int nt = 0; nt < 4; nt++) {
            int col = nb0 + wn * 32 + nt * 8 + c0;
            bbv[nt][0] = g_bb[col];
            bbv[nt][1] = g_bb[col + 1];
        }
        #pragma unroll
        for (int mt = 0; mt < 4; mt++) {
            int m0 = mb0 + wm * 64 + mt * 16 + r0;
            float rmin0 = INFINITY, rmin1 = INFINITY;
            #pragma unroll
            for (int nt = 0; nt < 4; nt++) {
                int col = nb0 + wn * 32 + nt * 8 + c0;
                float2 v0, v1;
                v0.x = bbv[nt][0] + acc[mt][nt][0];
                v0.y = bbv[nt][1] + acc[mt][nt][1];
                v1.x = bbv[nt][0] + acc[mt][nt][2];
                v1.y = bbv[nt][1] + acc[mt][nt][3];
                *(float2*)&g_S[(size_t)m0 * NUM + col]       = v0;
                *(float2*)&g_S[(size_t)(m0 + 8) * NUM + col] = v1;
                rmin0 = fminf(rmin0, fminf(v0.x, v0.y));
                rmin1 = fminf(rmin1, fminf(v1.x, v1.y));
            }
            rmin0 = fminf(rmin0, __shfl_xor_sync(0xffffffffu, rmin0, 1));
            rmin0 = fminf(rmin0, __shfl_xor_sync(0xffffffffu, rmin0, 2));
            rmin1 = fminf(rmin1, __shfl_xor_sync(0xffffffffu, rmin1, 1));
            rmin1 = fminf(rmin1, __shfl_xor_sync(0xffffffffu, rmin1, 2));
            if ((lane & 3) == 0) {
                int blk = (nb0 >> 5) + wn;
                g_BM[(size_t)m0 * NBLK + blk]       = rmin0;
                g_BM[(size_t)(m0 + 8) * NBLK + blk] = rmin1;
            }
        }
    }

    // ---- mirrored tile (off-diagonal only): one-shot 128x132 stage ----
    if (bx != by) {
        float bbr[4][2];
        #pragma unroll
        for (int mt = 0; mt < 4; mt++) {
            int m0 = mb0 + wm * 64 + mt * 16 + r0;
            bbr[mt][0] = g_bb[m0];
            bbr[mt][1] = g_bb[m0 + 8];
        }
        float* stage = (float*)smem;     // [128 cols][132] floats = 67.6KB
        // every warp writes its own (m-half, col-group) sub-tile: full coverage
        #pragma unroll
        for (int mt = 0; mt < 4; mt++) {
            int rl = wm * 64 + mt * 16 + r0;
            #pragma unroll
            for (int nt = 0; nt < 4; nt++) {
                int cl = wn * 32 + nt * 8 + c0;
                stage[cl * 132 + rl]           = bbr[mt][0] + acc[mt][nt][0];
                stage[(cl + 1) * 132 + rl]     = bbr[mt][0] + acc[mt][nt][1];
                stage[cl * 132 + rl + 8]       = bbr[mt][1] + acc[mt][nt][2];
                stage[(cl + 1) * 132 + rl + 8] = bbr[mt][1] + acc[mt][nt][3];
            }
        }
        __syncthreads();
        int cl  = tid >> 1;            // 0..127 mirrored row within tile
        int seg = (tid & 1) * 64;      // 0 or 64 (m columns)
        size_t orow = (size_t)(nb0 + cl) * NUM + mb0 + seg;
        float bmin0 = INFINITY, bmin1 = INFINITY;
        #pragma unroll
        for (int k2 = 0; k2 < 16; k2++) {
            float4 vv = *(float4*)&stage[cl * 132 + seg + k2 * 4];
            *(float4*)&g_S[orow + k2 * 4] = vv;
            float m4 = fminf(fminf(vv.x, vv.y), fminf(vv.z, vv.w));
            if (k2 < 8) bmin0 = fminf(bmin0, m4);
            else        bmin1 = fminf(bmin1, m4);
        }
        int bbase = (mb0 >> 5) + (seg >> 5);
        g_BM[(size_t)(nb0 + cl) * NBLK + bbase]     = bmin0;
        g_BM[(size_t)(nb0 + cl) * NBLK + bbase + 1] = bmin1;
    }
}

// ---------------------------------------------------------------
// top-K helpers (exact jax tie-break)
// ---------------------------------------------------------------
template <int K>
__device__ __forceinline__ void ins(float* v, int* ix, float s, int j) {
    bool better = (s < v[K - 1]) || (s == v[K - 1] && j < ix[K - 1]);
    if (better) {
        v[K - 1] = s; ix[K - 1] = j;
        #pragma unroll
        for (int t = K - 1; t > 0; t--) {
            bool sw = (v[t] < v[t - 1]) || (v[t] == v[t - 1] && ix[t] < ix[t - 1]);
            float tv = sw ? v[t - 1] : v[t];
            float bv = sw ? v[t] : v[t - 1];
            int   ti = sw ? ix[t - 1] : ix[t];
            int   bi = sw ? ix[t] : ix[t - 1];
            v[t] = tv; v[t - 1] = bv; ix[t] = ti; ix[t - 1] = bi;
        }
    }
}

template <int K>
__device__ __forceinline__ void warp_popk(float* v, int* ix, float* out_v, int* out_i) {
    #pragma unroll
    for (int r = 0; r < K; r++) {
        float bv = v[0]; int bi = ix[0];
        #pragma unroll
        for (int o = 16; o > 0; o >>= 1) {
            float ov = __shfl_xor_sync(0xffffffffu, bv, o);
            int   oi = __shfl_xor_sync(0xffffffffu, bi, o);
            if (ov < bv || (ov == bv && oi < bi)) { bv = ov; bi = oi; }
        }
        out_v[r] = bv; out_i[r] = bi;
        if (bv == v[0] && bi == ix[0]) {
            #pragma unroll
            for (int t = 0; t < K - 1; t++) { v[t] = v[t + 1]; ix[t] = ix[t + 1]; }
            v[K - 1] = INFINITY; ix[K - 1] = 0x7fffffff;
        }
    }
}

template <int K>
__device__ __forceinline__ float mode_k(const float* lab) {
    float best = 0.f; int bc = -1;
    #pragma unroll
    for (int a = 0; a < K; a++) {
        int c = 0;
        #pragma unroll
        for (int b = 0; b < K; b++) c += (lab[a] == lab[b]);
        if (c > bc || (c == bc && lab[a] < best)) { bc = c; best = lab[a]; }
    }
    return best;
}

// mixup: warp per row; 128 block-mins (cols 0..4095) -> T -> scan candidates
__global__ void topk_mixup_kernel() {
    int warp = (blockIdx.x * blockDim.x + threadIdx.x) >> 5;
    int lane = threadIdx.x & 31;
    if (warp >= N0) return;
    const float* Srow = g_S + (size_t)(N0 + warp) * NUM;
    const float* BMrow = g_BM + (size_t)(N0 + warp) * NBLK;
    float4 bm4 = *(const float4*)(BMrow + lane * 4);
    float bmv[4] = {bm4.x, bm4.y, bm4.z, bm4.w};

    float v[11]; int ix[11];
    #pragma unroll
    for (int t = 0; t < 11; t++) { v[t] = INFINITY; ix[t] = 0x7fffffff; }
    #pragma unroll
    for (int e = 0; e < 4; e++) ins<11>(v, ix, bmv[e], lane * 4 + e);
    float tv[11]; int ti[11];
    warp_popk<11>(v, ix, tv, ti);
    float T = tv[10];

    #pragma unroll
    for (int t = 0; t < 11; t++) { v[t] = INFINITY; ix[t] = 0x7fffffff; }
    #pragma unroll
    for (int e = 0; e < 4; e++) {
        unsigned m = __ballot_sync(0xffffffffu, bmv[e] <= T);
        while (m) {
            int L = __ffs(m) - 1; m &= m - 1;
            int bk = L * 4 + e;
            int j = bk * 32 + lane;
            ins<11>(v, ix, Srow[j], j);
        }
    }
    warp_popk<11>(v, ix, tv, ti);
    if (lane == 0) {
        float lab[11];
        #pragma unroll
        for (int t = 0; t < 11; t++) lab[t] = g_y2[ti[t]];
        g_y2[N0 + warp] = mode_k<11>(lab);
    }
}

// knn: warp per row; 256 block-mins -> T -> scan candidates
__global__ void topk_knn_kernel() {
    int warp = (blockIdx.x * blockDim.x + threadIdx.x) >> 5;
    int lane = threadIdx.x & 31;
    if (warp >= NUM) return;
    const float* Srow = g_S + (size_t)warp * NUM;
    const float* BMrow = g_BM + (size_t)warp * NBLK;
    float4 a0 = *(const float4*)(BMrow + lane * 8);
    float4 a1 = *(const float4*)(BMrow + lane * 8 + 4);
    float bmv[8] = {a0.x, a0.y, a0.z, a0.w, a1.x, a1.y, a1.z, a1.w};

    float v[4]; int ix[4];
    #pragma unroll
    for (int t = 0; t < 4; t++) { v[t] = INFINITY; ix[t] = 0x7fffffff; }
    #pragma unroll
    for (int e = 0; e < 8; e++) ins<4>(v, ix, bmv[e], lane * 8 + e);
    float tv[4]; int ti[4];
    warp_popk<4>(v, ix, tv, ti);
    float T = tv[3];

    #pragma unroll
    for (int t = 0; t < 4; t++) { v[t] = INFINITY; ix[t] = 0x7fffffff; }
    #pragma unroll
    for (int e = 0; e < 8; e++) {
        unsigned m = __ballot_sync(0xffffffffu, bmv[e] <= T);
        while (m) {
            int L = __ffs(m) - 1; m &= m - 1;
            int bk = L * 8 + e;
            int j = bk * 32 + lane;
            ins<4>(v, ix, Srow[j], j);
        }
    }
    warp_popk<4>(v, ix, tv, ti);
    if (lane == 0) {
        float lab[3];
        lab[0] = g_y2[ti[1]]; lab[1] = g_y2[ti[2]]; lab[2] = g_y2[ti[3]];
        float m = mode_k<3>(lab);
        float d = m - g_y2[warp];
        g_ptknn[warp] = d * d;
    }
}

// ---------------------------------------------------------------
// class statistics + gm loss + final reduce
// ---------------------------------------------------------------
__global__ void zero_stats_kernel() {
    int i = blockIdx.x * blockDim.x + threadIdx.x;
    if (i < CLASSES * DD) g_musum[i] = 0.f;
    if (i < CLASSES)      g_cnt[i]   = 0.f;
}

__global__ void scatter_kernel() {
    int i = blockIdx.x;
    int tid = threadIdx.x;
    int c = (int)g_y2[i];
    const float* xr = g_x2 + (size_t)i * DD;
    for (int d = tid; d < DD; d += 128)
        atomicAdd(&g_musum[c * DD + d], xr[d]);
    if (tid == 0) atomicAdd(&g_cnt[c], 1.f);
}

__global__ void mu_kernel() {
    int c = blockIdx.x, tid = threadIdx.x;
    float inv = 1.f / fmaxf(g_cnt[c], 1.f);
    float ss = 0.f;
    for (int d = tid; d < DD; d += 128) {
        float m = g_musum[c * DD + d] * inv;
        g_mu[c * DD + d] = m;
        ss += m * m;
    }
    __shared__ float red[128];
    red[tid] = ss;
    __syncthreads();
    #pragma unroll
    for (int s = 64; s > 0; s >>= 1) {
        if (tid < s) red[tid] += red[tid + s];
        __syncthreads();
    }
    if (tid == 0) g_mumu[c] = red[0];
}

// 16 points per block; 50 threads x 2 classes (halves LDS traffic)
#define GMP 16
__global__ void gm_kernel() {
    int i0 = blockIdx.x * GMP, tid = threadIdx.x;
    int wid = tid >> 5, lane = tid & 31;
    __shared__ float xs[GMP][DD];
    for (int t = tid; t < GMP * DD / 4; t += 128) {
        int p = t / (DD / 4), k = t % (DD / 4);
        ((float4*)xs[p])[k] = ((const float4*)(g_x2 + (size_t)(i0 + p) * DD))[k];
    }
    __syncthreads();

    float w0[GMP], w1[GMP];
    #pragma unroll
    for (int p = 0; p < GMP; p++) { w0[p] = 0.f; w1[p] = 0.f; }
    int c1 = tid, c2 = tid + 50;
    if (tid < 50) {
        const float4* mua = (const float4*)(g_mu + c1 * DD);
        const float4* mub = (const float4*)(g_mu + c2 * DD);
        float d0[GMP], d1[GMP];
        #pragma unroll
        for (int p = 0; p < GMP; p++) { d0[p] = 0.f; d1[p] = 0.f; }
        for (int k = 0; k < DD / 4; k++) {
            float4 ba = mua[k];
            float4 bb4 = mub[k];
            #pragma unroll
            for (int p = 0; p < GMP; p++) {
                float4 a = ((const float4*)xs[p])[k];
                d0[p] = fmaf(a.x, ba.x, d0[p]);
                d0[p] = fmaf(a.y, ba.y, d0[p]);
                d0[p] = fmaf(a.z, ba.z, d0[p]);
                d0[p] = fmaf(a.w, ba.w, d0[p]);
                d1[p] = fmaf(a.x, bb4.x, d1[p]);
                d1[p] = fmaf(a.y, bb4.y, d1[p]);
                d1[p] = fmaf(a.z, bb4.z, d1[p]);
                d1[p] = fmaf(a.w, bb4.w, d1[p]);
            }
        }
        float l0 = (g_cnt[c1] > 0.f) ? 1.f : 0.f;
        float l1 = (g_cnt[c2] > 0.f) ? 1.f : 0.f;
        float mm0 = g_mumu[c1], mm1 = g_mumu[c2];
        #pragma unroll
        for (int p = 0; p < GMP; p++) {
            float bbp = g_bb[i0 + p];
            w0[p] = l0 * expf(-0.5f * (bbp + mm0 - 2.f * d0[p]));
            w1[p] = l1 * expf(-0.5f * (bbp + mm1 - 2.f * d1[p]));
        }
    }
    __shared__ float wred[4], tred[4];
    for (int p = 0; p < GMP; p++) {
        float s = w0[p] + w1[p];
        #pragma unroll
        for (int o = 16; o > 0; o >>= 1) s += __shfl_xor_sync(0xffffffffu, s, o);
        if (lane == 0) wred[wid] = s;
        __syncthreads();
        float wsum = wred[0] + wred[1] + wred[2] + wred[3];
        float t = 0.f;
        if (tid < 50) {
            int yi = (int)g_y2[i0 + p];
            float pp0 = fminf(fmaxf(w0[p] / (wsum + 1e-15f), 0.f), 1.f);
            float dd0 = pp0 - ((c1 == yi) ? 1.f : 0.f);
            float pp1 = fminf(fmaxf(w1[p] / (wsum + 1e-15f), 0.f), 1.f);
            float dd1 = pp1 - ((c2 == yi) ? 1.f : 0.f);
            t = dd0 * dd0 + dd1 * dd1;
        }
        #pragma unroll
        for (int o = 16; o > 0; o >>= 1) t += __shfl_xor_sync(0xffffffffu, t, o);
        if (lane == 0) tred[wid] = t;
        __syncthreads();
        if (tid == 0) g_ptgm[i0 + p] = tred[0] + tred[1] + tred[2] + tred[3];
        __syncthreads();
    }
}

__global__ void final_kernel(float* __restrict__ out) {
    __shared__ float red[256];
    int tid = threadIdx.x;
    float s1 = 0.f, s2 = 0.f;
    for (int i = tid; i < NUM; i += 256) { s1 += g_ptgm[i]; s2 += g_ptknn[i]; }
    red[tid] = s1;
    __syncthreads();
    #pragma unroll
    for (int s = 128; s > 0; s >>= 1) {
        if (tid < s) red[tid] += red[tid + s];
        __syncthreads();
    }
    float t1 = red[0];
    __syncthreads();
    red[tid] = s2;
    __syncthreads();
    #pragma unroll
    for (int s = 128; s > 0; s >>= 1) {
        if (tid < s) red[tid] += red[tid + s];
        __syncthreads();
    }
    if (tid == 0) out[0] = t1 / (float)NUM + 0.01f * red[0] / (float)NUM;
}

// ---------------------------------------------------------------
extern "C" void kernel_launch(void* const* d_in, const int* in_sizes, int n_in,
                              void* d_out, int out_size) {
    const float* x    = (const float*)d_in[0];
    const float* y    = (const float*)d_in[1];
    const float* lam  = (const float*)d_in[2];
    const int*   perm = (const int*)d_in[3];
    float* out = (float*)d_out;

    cudaFuncSetAttribute(gemm_mma, cudaFuncAttributeMaxDynamicSharedMemorySize, GEMM_SMEM);

    build_kernel<<<NUM, 128>>>(x, y, lam, perm);

    // compact triangular distance GEMM (diag last) + mirror + block minima
    gemm_mma<<<NTRI, 256, GEMM_SMEM>>>();

    topk_mixup_kernel<<<N0 / 8, 256>>>();
    topk_knn_kernel<<<NUM / 8, 256>>>();

    zero_stats_kernel<<<(CLASSES * DD + 255) / 256, 256>>>();
    scatter_kernel<<<NUM, 128>>>();
    mu_kernel<<<CLASSES, 128>>>();
    gm_kernel<<<NUM / GMP, 128>>>();

    final_kernel<<<1, 256>>>(out);
}

// round 15
// speedup vs baseline: 1.2204x; 1.2204x over previous
#include <cuda_runtime.h>
#include <cuda_bf16.h>
#include <cstdint>

#define N0      4096
#define NUM     8192
#define DD      512
#define KSP     1024          // 2-term split: A=[hi|lo](-2x)  B=[hi|hi](x)
#define CLASSES 100
#define NCH     16            // 1024 / 64
#define STAGE_BYTES 32768     // 16KB A + 16KB B
#define GEMM_SMEM 67712       // max(2 stages 64KB, 128x132 f32 stage 67.6KB)
#define NBLK    256           // 32-col blocks per row
#define NTRI    2080          // 2016 strict-lower + 64 diagonal

// ---- device scratch ----
__device__ float g_x2[(size_t)NUM * DD];
__device__ float g_bb[NUM];
__device__ float g_y2[NUM];
__device__ float g_S[(size_t)NUM * NUM];
__device__ float g_BM[(size_t)NUM * NBLK];          // per-32-col block minima
__device__ __nv_bfloat16 g_A2[(size_t)NUM * KSP];   // [hi|lo] of -2*x2 (exact split)
__device__ __nv_bfloat16 g_B2[(size_t)NUM * KSP];   // [hi|hi] of x2
__device__ float g_musum[CLASSES * DD];
__device__ float g_cnt[CLASSES];
__device__ float g_mu[CLASSES * DD];
__device__ float g_mumu[CLASSES];
__device__ float g_ptgm[NUM];
__device__ float g_ptknn[NUM];

__device__ __forceinline__ uint32_t smem_u32(const void* p) {
    uint32_t a;
    asm("{ .reg .u64 t; cvta.to.shared.u64 t, %1; cvt.u32.u64 %0, t; }" : "=r"(a) : "l"(p));
    return a;
}
__device__ __forceinline__ void cp16(uint32_t dst, const void* src) {
    asm volatile("cp.async.cg.shared.global [%0], [%1], 16;" :: "r"(dst), "l"(src));
}
__device__ __forceinline__ void ldm_x4(uint32_t addr, uint32_t& d0, uint32_t& d1,
                                       uint32_t& d2, uint32_t& d3) {
    asm volatile("ldmatrix.sync.aligned.m8n8.x4.shared.b16 {%0,%1,%2,%3}, [%4];"
                 : "=r"(d0), "=r"(d1), "=r"(d2), "=r"(d3) : "r"(addr));
}
__device__ __forceinline__ void mma_bf16(float* c, const uint32_t* a, uint32_t b0, uint32_t b1) {
    asm volatile("mma.sync.aligned.m16n8k16.row.col.f32.bf16.bf16.f32 "
                 "{%0,%1,%2,%3},{%4,%5,%6,%7},{%8,%9},{%0,%1,%2,%3};"
                 : "+f"(c[0]), "+f"(c[1]), "+f"(c[2]), "+f"(c[3])
                 : "r"(a[0]), "r"(a[1]), "r"(a[2]), "r"(a[3]), "r"(b0), "r"(b1));
}
__device__ __forceinline__ uint32_t pk(__nv_bfloat16 a, __nv_bfloat16 b) {
    union { __nv_bfloat162 h; uint32_t u; } t;
    t.h = __nv_bfloat162(a, b);
    return t.u;
}

// ---------------------------------------------------------------
// build: x2, bb, y lower half, and 2-term bf16 split operands
// ---------------------------------------------------------------
__global__ void build_kernel(const float* __restrict__ x, const float* __restrict__ y,
                             const float* __restrict__ lamp, const int* __restrict__ perm) {
    int row = blockIdx.x;
    int tid = threadIdx.x;
    float4 v;
    if (row < N0) {
        v = ((const float4*)(x + (size_t)row * DD))[tid];
        if (tid == 0) g_y2[row] = y[row];
    } else {
        int j = row - N0;
        float lam = *lamp, oml = 1.f - lam;
        int p = perm[j];
        float4 va = ((const float4*)(x + (size_t)j * DD))[tid];
        float4 vb = ((const float4*)(x + (size_t)p * DD))[tid];
        v.x = va.x * lam + vb.x * oml;
        v.y = va.y * lam + vb.y * oml;
        v.z = va.z * lam + vb.z * oml;
        v.w = va.w * lam + vb.w * oml;
    }
    ((float4*)(g_x2 + (size_t)row * DD))[tid] = v;
    float ss = v.x * v.x + v.y * v.y + v.z * v.z + v.w * v.w;

    float f[4] = {v.x, v.y, v.z, v.w};
    __nv_bfloat16* A = g_A2 + (size_t)row * KSP;
    __nv_bfloat16* B = g_B2 + (size_t)row * KSP;
    #pragma unroll
    for (int e = 0; e < 4; e += 2) {
        int d = tid * 4 + e;
        __nv_bfloat16 hb0, ha0, la0, hb1, ha1, la1;
        {
            float fb = f[e];
            hb0 = __float2bfloat16(fb);
            float fa = -2.f * fb;
            ha0 = __float2bfloat16(fa);
            la0 = __float2bfloat16(fa - __bfloat162float(ha0));
        }
        {
            float fb = f[e + 1];
            hb1 = __float2bfloat16(fb);
            float fa = -2.f * fb;
            ha1 = __float2bfloat16(fa);
            la1 = __float2bfloat16(fa - __bfloat162float(ha1));
        }
        *(uint32_t*)(A + d)       = pk(ha0, ha1);
        *(uint32_t*)(A + d + 512) = pk(la0, la1);
        *(uint32_t*)(B + d)       = pk(hb0, hb1);
        *(uint32_t*)(B + d + 512) = pk(hb0, hb1);
    }

    __shared__ float red[128];
    red[tid] = ss;
    __syncthreads();
    #pragma unroll
    for (int s = 64; s > 0; s >>= 1) {
        if (tid < s) red[tid] += red[tid + s];
        __syncthreads();
    }
    if (tid == 0) g_bb[row] = red[0];
}

// ---------------------------------------------------------------
// mma.sync distance GEMM, compact triangular grid (diagonal tiles LAST),
// mirror + 32-col block minima.  K=1024 (2-term split).
// CTA 128x128, 8 warps (2x4), warp tile 64x32, BK=64, 2-stage cp.async
// ---------------------------------------------------------------
__global__ __launch_bounds__(256, 2) void gemm_mma() {
    int b = blockIdx.x;
    int by, bx;
    if (b < 2016) {            // strict lower triangle
        by = (int)((1.f + sqrtf(8.f * (float)b + 1.f)) * 0.5f);
        while (by * (by - 1) / 2 > b) by--;
        while ((by + 1) * by / 2 <= b) by++;
        bx = b - by * (by - 1) / 2;
    } else {                   // diagonal tiles last (light: no mirror)
        by = bx = b - 2016;
    }

    extern __shared__ char smem[];
    const int tid  = threadIdx.x;
    const int lane = tid & 31;
    const int w    = tid >> 5;
    const int wm   = w >> 2, wn = w & 3;
    const uint32_t sbase = smem_u32(smem);

    const char* gA = (const char*)(g_A2 + (size_t)(by * 128) * KSP);
    const char* gB = (const char*)(g_B2 + (size_t)(bx * 128) * KSP);

    const int lrow = tid >> 3;   // 0..31
    const int lseg = tid & 7;

    float acc[4][4][4];
    #pragma unroll
    for (int mt = 0; mt < 4; mt++)
        #pragma unroll
        for (int nt = 0; nt < 4; nt++)
            #pragma unroll
            for (int e = 0; e < 4; e++) acc[mt][nt][e] = 0.f;

    #define ISSUE(chunk, stg)                                                        \
    {                                                                                \
        uint32_t sA = sbase + (stg) * STAGE_BYTES;                                   \
        uint32_t sB = sA + 16384;                                                    \
        _Pragma("unroll")                                                            \
        for (int r = 0; r < 4; r++) {                                                \
            int row = lrow + r * 32;                                                 \
            uint32_t d = (uint32_t)(row * 128 + ((lseg ^ (row & 7)) * 16));          \
            cp16(sA + d, gA + (size_t)row * (KSP * 2) + (chunk) * 128 + lseg * 16);  \
            cp16(sB + d, gB + (size_t)row * (KSP * 2) + (chunk) * 128 + lseg * 16);  \
        }                                                                            \
        asm volatile("cp.async.commit_group;" ::: "memory");                         \
    }

    ISSUE(0, 0);
    for (int i = 0; i < NCH; i++) {
        const int stg = i & 1;
        if (i + 1 < NCH) {
            ISSUE(i + 1, stg ^ 1);
            asm volatile("cp.async.wait_group 1;" ::: "memory");
        } else {
            asm volatile("cp.async.wait_group 0;" ::: "memory");
        }
        __syncthreads();

        const uint32_t sA = sbase + stg * STAGE_BYTES;
        const uint32_t sB = sA + 16384;
        #pragma unroll
        for (int kk = 0; kk < 4; kk++) {
            const int half = lane >> 4;
            uint32_t a[4][4];
            #pragma unroll
            for (int mt = 0; mt < 4; mt++) {
                int row = wm * 64 + mt * 16 + (lane & 15);
                uint32_t ad = sA + row * 128 + (((kk * 2 + half) ^ (row & 7)) * 16);
                ldm_x4(ad, a[mt][0], a[mt][1], a[mt][2], a[mt][3]);
            }
            uint32_t bfr[2][4];
            #pragma unroll
            for (int pt = 0; pt < 2; pt++) {
                int nrow = wn * 32 + pt * 16 + ((lane >> 3) & 1) * 8 + (lane & 7);
                uint32_t bd = sB + nrow * 128 + (((kk * 2 + half) ^ (nrow & 7)) * 16);
                ldm_x4(bd, bfr[pt][0], bfr[pt][1], bfr[pt][2], bfr[pt][3]);
            }
            #pragma unroll
            for (int mt = 0; mt < 4; mt++)
                #pragma unroll
                for (int nt = 0; nt < 4; nt++) {
                    int pt = nt >> 1, sub = nt & 1;
                    mma_bf16(acc[mt][nt], a[mt], bfr[pt][sub], bfr[pt][sub + 2]);
                }
        }
        __syncthreads();
    }
    #undef ISSUE

    const int mb0 = by * 128, nb0 = bx * 128;
    const int r0 = lane >> 2;
    const int c0 = (lane & 3) * 2;

    // ---- straight tile + 32-col block minima ----
    {
        float bbv[4][2];
        #pragma unroll
        for (int nt = 0; nt < 4; nt++) {
            int col = nb0 + wn * 32 + nt * 8 + c0;
            bbv[nt][0] = g_bb[col];
            bbv[nt][1] = g_bb[col + 1];
        }
        #pragma unroll
        for (int mt = 0; mt < 4; mt++) {
            int m0 = mb0 + wm * 64 + mt * 16 + r0;
            float rmin0 = INFINITY, rmin1 = INFINITY;
            #pragma unroll
            for (int nt = 0; nt < 4; nt++) {
                int col = nb0 + wn * 32 + nt * 8 + c0;
                float2 v0, v1;
                v0.x = bbv[nt][0] + acc[mt][nt][0];
                v0.y = bbv[nt][1] + acc[mt][nt][1];
                v1.x = bbv[nt][0] + acc[mt][nt][2];
                v1.y = bbv[nt][1] + acc[mt][nt][3];
                *(float2*)&g_S[(size_t)m0 * NUM + col]       = v0;
                *(float2*)&g_S[(size_t)(m0 + 8) * NUM + col] = v1;
                rmin0 = fminf(rmin0, fminf(v0.x, v0.y));
                rmin1 = fminf(rmin1, fminf(v1.x, v1.y));
            }
            rmin0 = fminf(rmin0, __shfl_xor_sync(0xffffffffu, rmin0, 1));
            rmin0 = fminf(rmin0, __shfl_xor_sync(0xffffffffu, rmin0, 2));
            rmin1 = fminf(rmin1, __shfl_xor_sync(0xffffffffu, rmin1, 1));
            rmin1 = fminf(rmin1, __shfl_xor_sync(0xffffffffu, rmin1, 2));
            if ((lane & 3) == 0) {
                int blk = (nb0 >> 5) + wn;
                g_BM[(size_t)m0 * NBLK + blk]       = rmin0;
                g_BM[(size_t)(m0 + 8) * NBLK + blk] = rmin1;
            }
        }
    }

    // ---- mirrored tile (off-diagonal only): one-shot 128x132 stage ----
    if (bx != by) {
        float bbr[4][2];
        #pragma unroll
        for (int mt = 0; mt < 4; mt++) {
            int m0 = mb0 + wm * 64 + mt * 16 + r0;
            bbr[mt][0] = g_bb[m0];
            bbr[mt][1] = g_bb[m0 + 8];
        }
        float* stage = (float*)smem;     // [128 cols][132] floats
        #pragma unroll
        for (int mt = 0; mt < 4; mt++) {
            int rl = wm * 64 + mt * 16 + r0;
            #pragma unroll
            for (int nt = 0; nt < 4; nt++) {
                int cl = wn * 32 + nt * 8 + c0;
                stage[cl * 132 + rl]           = bbr[mt][0] + acc[mt][nt][0];
                stage[(cl + 1) * 132 + rl]     = bbr[mt][0] + acc[mt][nt][1];
                stage[cl * 132 + rl + 8]       = bbr[mt][1] + acc[mt][nt][2];
                stage[(cl + 1) * 132 + rl + 8] = bbr[mt][1] + acc[mt][nt][3];
            }
        }
        __syncthreads();
        int cl  = tid >> 1;
        int seg = (tid & 1) * 64;
        size_t orow = (size_t)(nb0 + cl) * NUM + mb0 + seg;
        float bmin0 = INFINITY, bmin1 = INFINITY;
        #pragma unroll
        for (int k2 = 0; k2 < 16; k2++) {
            float4 vv = *(float4*)&stage[cl * 132 + seg + k2 * 4];
            *(float4*)&g_S[orow + k2 * 4] = vv;
            float m4 = fminf(fminf(vv.x, vv.y), fminf(vv.z, vv.w));
            if (k2 < 8) bmin0 = fminf(bmin0, m4);
            else        bmin1 = fminf(bmin1, m4);
        }
        int bbase = (mb0 >> 5) + (seg >> 5);
        g_BM[(size_t)(nb0 + cl) * NBLK + bbase]     = bmin0;
        g_BM[(size_t)(nb0 + cl) * NBLK + bbase + 1] = bmin1;
    }
}

// ---------------------------------------------------------------
// top-K helpers (exact jax tie-break)
// ---------------------------------------------------------------
template <int K>
__device__ __forceinline__ void ins(float* v, int* ix, float s, int j) {
    bool better = (s < v[K - 1]) || (s == v[K - 1] && j < ix[K - 1]);
    if (better) {
        v[K - 1] = s; ix[K - 1] = j;
        #pragma unroll
        for (int t = K - 1; t > 0; t--) {
            bool sw = (v[t] < v[t - 1]) || (v[t] == v[t - 1] && ix[t] < ix[t - 1]);
            float tv = sw ? v[t - 1] : v[t];
            float bv = sw ? v[t] : v[t - 1];
            int   ti = sw ? ix[t - 1] : ix[t];
            int   bi = sw ? ix[t] : ix[t - 1];
            v[t] = tv; v[t - 1] = bv; ix[t] = ti; ix[t - 1] = bi;
        }
    }
}

template <int K>
__device__ __forceinline__ void warp_popk(float* v, int* ix, float* out_v, int* out_i) {
    #pragma unroll
    for (int r = 0; r < K; r++) {
        float bv = v[0]; int bi = ix[0];
        #pragma unroll
        for (int o = 16; o > 0; o >>= 1) {
            float ov = __shfl_xor_sync(0xffffffffu, bv, o);
            int   oi = __shfl_xor_sync(0xffffffffu, bi, o);
            if (ov < bv || (ov == bv && oi < bi)) { bv = ov; bi = oi; }
        }
        out_v[r] = bv; out_i[r] = bi;
        if (bv == v[0] && bi == ix[0]) {
            #pragma unroll
            for (int t = 0; t < K - 1; t++) { v[t] = v[t + 1]; ix[t] = ix[t + 1]; }
            v[K - 1] = INFINITY; ix[K - 1] = 0x7fffffff;
        }
    }
}

template <int K>
__device__ __forceinline__ float mode_k(const float* lab) {
    float best = 0.f; int bc = -1;
    #pragma unroll
    for (int a = 0; a < K; a++) {
        int c = 0;
        #pragma unroll
        for (int b = 0; b < K; b++) c += (lab[a] == lab[b]);
        if (c > bc || (c == bc && lab[a] < best)) { bc = c; best = lab[a]; }
    }
    return best;
}

// mixup: warp per row; 128 block-mins (cols 0..4095) -> T -> scan candidates
__global__ void topk_mixup_kernel() {
    int warp = (blockIdx.x * blockDim.x + threadIdx.x) >> 5;
    int lane = threadIdx.x & 31;
    if (warp >= N0) return;
    const float* Srow = g_S + (size_t)(N0 + warp) * NUM;
    const float* BMrow = g_BM + (size_t)(N0 + warp) * NBLK;
    float4 bm4 = *(const float4*)(BMrow + lane * 4);
    float bmv[4] = {bm4.x, bm4.y, bm4.z, bm4.w};

    float v[11]; int ix[11];
    #pragma unroll
    for (int t = 0; t < 11; t++) { v[t] = INFINITY; ix[t] = 0x7fffffff; }
    #pragma unroll
    for (int e = 0; e < 4; e++) ins<11>(v, ix, bmv[e], lane * 4 + e);
    float tv[11]; int ti[11];
    warp_popk<11>(v, ix, tv, ti);
    float T = tv[10];

    #pragma unroll
    for (int t = 0; t < 11; t++) { v[t] = INFINITY; ix[t] = 0x7fffffff; }
    #pragma unroll
    for (int e = 0; e < 4; e++) {
        unsigned m = __ballot_sync(0xffffffffu, bmv[e] <= T);
        while (m) {
            int L = __ffs(m) - 1; m &= m - 1;
            int bk = L * 4 + e;
            int j = bk * 32 + lane;
            ins<11>(v, ix, Srow[j], j);
        }
    }
    warp_popk<11>(v, ix, tv, ti);
    if (lane == 0) {
        float lab[11];
        #pragma unroll
        for (int t = 0; t < 11; t++) lab[t] = g_y2[ti[t]];
        g_y2[N0 + warp] = mode_k<11>(lab);
    }
}

// knn: warp per row; 256 block-mins -> T -> scan candidates
__global__ void topk_knn_kernel() {
    int warp = (blockIdx.x * blockDim.x + threadIdx.x) >> 5;
    int lane = threadIdx.x & 31;
    if (warp >= NUM) return;
    const float* Srow = g_S + (size_t)warp * NUM;
    const float* BMrow = g_BM + (size_t)warp * NBLK;
    float4 a0 = *(const float4*)(BMrow + lane * 8);
    float4 a1 = *(const float4*)(BMrow + lane * 8 + 4);
    float bmv[8] = {a0.x, a0.y, a0.z, a0.w, a1.x, a1.y, a1.z, a1.w};

    float v[4]; int ix[4];
    #pragma unroll
    for (int t = 0; t < 4; t++) { v[t] = INFINITY; ix[t] = 0x7fffffff; }
    #pragma unroll
    for (int e = 0; e < 8; e++) ins<4>(v, ix, bmv[e], lane * 8 + e);
    float tv[4]; int ti[4];
    warp_popk<4>(v, ix, tv, ti);
    float T = tv[3];

    #pragma unroll
    for (int t = 0; t < 4; t++) { v[t] = INFINITY; ix[t] = 0x7fffffff; }
    #pragma unroll
    for (int e = 0; e < 8; e++) {
        unsigned m = __ballot_sync(0xffffffffu, bmv[e] <= T);
        while (m) {
            int L = __ffs(m) - 1; m &= m - 1;
            int bk = L * 8 + e;
            int j = bk * 32 + lane;
            ins<4>(v, ix, Srow[j], j);
        }
    }
    warp_popk<4>(v, ix, tv, ti);
    if (lane == 0) {
        float lab[3];
        lab[0] = g_y2[ti[1]]; lab[1] = g_y2[ti[2]]; lab[2] = g_y2[ti[3]];
        float m = mode_k<3>(lab);
        float d = m - g_y2[warp];
        g_ptknn[warp] = d * d;
    }
}

// ---------------------------------------------------------------
// class statistics + gm loss + final reduce
// ---------------------------------------------------------------
__global__ void zero_stats_kernel() {
    int i = blockIdx.x * blockDim.x + threadIdx.x;
    if (i < CLASSES * DD) g_musum[i] = 0.f;
    if (i < CLASSES)      g_cnt[i]   = 0.f;
}

__global__ void scatter_kernel() {
    int i = blockIdx.x;
    int tid = threadIdx.x;
    int c = (int)g_y2[i];
    const float* xr = g_x2 + (size_t)i * DD;
    for (int d = tid; d < DD; d += 128)
        atomicAdd(&g_musum[c * DD + d], xr[d]);
    if (tid == 0) atomicAdd(&g_cnt[c], 1.f);
}

__global__ void mu_kernel() {
    int c = blockIdx.x, tid = threadIdx.x;
    float inv = 1.f / fmaxf(g_cnt[c], 1.f);
    float ss = 0.f;
    for (int d = tid; d < DD; d += 128) {
        float m = g_musum[c * DD + d] * inv;
        g_mu[c * DD + d] = m;
        ss += m * m;
    }
    __shared__ float red[128];
    red[tid] = ss;
    __syncthreads();
    #pragma unroll
    for (int s = 64; s > 0; s >>= 1) {
        if (tid < s) red[tid] += red[tid + s];
        __syncthreads();
    }
    if (tid == 0) g_mumu[c] = red[0];
}

// 16 points per block; 50 threads x 2 classes (halves LDS traffic)
#define GMP 16
__global__ void gm_kernel() {
    int i0 = blockIdx.x * GMP, tid = threadIdx.x;
    int wid = tid >> 5, lane = tid & 31;
    __shared__ float xs[GMP][DD];
    for (int t = tid; t < GMP * DD / 4; t += 128) {
        int p = t / (DD / 4), k = t % (DD / 4);
        ((float4*)xs[p])[k] = ((const float4*)(g_x2 + (size_t)(i0 + p) * DD))[k];
    }
    __syncthreads();

    float w0[GMP], w1[GMP];
    #pragma unroll
    for (int p = 0; p < GMP; p++) { w0[p] = 0.f; w1[p] = 0.f; }
    int c1 = tid, c2 = tid + 50;
    if (tid < 50) {
        const float4* mua = (const float4*)(g_mu + c1 * DD);
        const float4* mub = (const float4*)(g_mu + c2 * DD);
        float d0[GMP], d1[GMP];
        #pragma unroll
        for (int p = 0; p < GMP; p++) { d0[p] = 0.f; d1[p] = 0.f; }
        for (int k = 0; k < DD / 4; k++) {
            float4 ba = mua[k];
            float4 bb4 = mub[k];
            #pragma unroll
            for (int p = 0; p < GMP; p++) {
                float4 a = ((const float4*)xs[p])[k];
                d0[p] = fmaf(a.x, ba.x, d0[p]);
                d0[p] = fmaf(a.y, ba.y, d0[p]);
                d0[p] = fmaf(a.z, ba.z, d0[p]);
                d0[p] = fmaf(a.w, ba.w, d0[p]);
                d1[p] = fmaf(a.x, bb4.x, d1[p]);
                d1[p] = fmaf(a.y, bb4.y, d1[p]);
                d1[p] = fmaf(a.z, bb4.z, d1[p]);
                d1[p] = fmaf(a.w, bb4.w, d1[p]);
            }
        }
        float l0 = (g_cnt[c1] > 0.f) ? 1.f : 0.f;
        float l1 = (g_cnt[c2] > 0.f) ? 1.f : 0.f;
        float mm0 = g_mumu[c1], mm1 = g_mumu[c2];
        #pragma unroll
        for (int p = 0; p < GMP; p++) {
            float bbp = g_bb[i0 + p];
            w0[p] = l0 * expf(-0.5f * (bbp + mm0 - 2.f * d0[p]));
            w1[p] = l1 * expf(-0.5f * (bbp + mm1 - 2.f * d1[p]));
        }
    }
    __shared__ float wred[4], tred[4];
    for (int p = 0; p < GMP; p++) {
        float s = w0[p] + w1[p];
        #pragma unroll
        for (int o = 16; o > 0; o >>= 1) s += __shfl_xor_sync(0xffffffffu, s, o);
        if (lane == 0) wred[wid] = s;
        __syncthreads();
        float wsum = wred[0] + wred[1] + wred[2] + wred[3];
        float t = 0.f;
        if (tid < 50) {
            int yi = (int)g_y2[i0 + p];
            float pp0 = fminf(fmaxf(w0[p] / (wsum + 1e-15f), 0.f), 1.f);
            float dd0 = pp0 - ((c1 == yi) ? 1.f : 0.f);
            float pp1 = fminf(fmaxf(w1[p] / (wsum + 1e-15f), 0.f), 1.f);
            float dd1 = pp1 - ((c2 == yi) ? 1.f : 0.f);
            t = dd0 * dd0 + dd1 * dd1;
        }
        #pragma unroll
        for (int o = 16; o > 0; o >>= 1) t += __shfl_xor_sync(0xffffffffu, t, o);
        if (lane == 0) tred[wid] = t;
        __syncthreads();
        if (tid == 0) g_ptgm[i0 + p] = tred[0] + tred[1] + tred[2] + tred[3];
        __syncthreads();
    }
}

__global__ void final_kernel(float* __restrict__ out) {
    __shared__ float red[256];
    int tid = threadIdx.x;
    float s1 = 0.f, s2 = 0.f;
    for (int i = tid; i < NUM; i += 256) { s1 += g_ptgm[i]; s2 += g_ptknn[i]; }
    red[tid] = s1;
    __syncthreads();
    #pragma unroll
    for (int s = 128; s > 0; s >>= 1) {
        if (tid < s) red[tid] += red[tid + s];
        __syncthreads();
    }
    float t1 = red[0];
    __syncthreads();
    red[tid] = s2;
    __syncthreads();
    #pragma unroll
    for (int s = 128; s > 0; s >>= 1) {
        if (tid < s) red[tid] += red[tid + s];
        __syncthreads();
    }
    if (tid == 0) out[0] = t1 / (float)NUM + 0.01f * red[0] / (float)NUM;
}

// ---------------------------------------------------------------
extern "C" void kernel_launch(void* const* d_in, const int* in_sizes, int n_in,
                              void* d_out, int out_size) {
    const float* x    = (const float*)d_in[0];
    const float* y    = (const float*)d_in[1];
    const float* lam  = (const float*)d_in[2];
    const int*   perm = (const int*)d_in[3];
    float* out = (float*)d_out;

    cudaFuncSetAttribute(gemm_mma, cudaFuncAttributeMaxDynamicSharedMemorySize, GEMM_SMEM);

    build_kernel<<<NUM, 128>>>(x, y, lam, perm);

    // compact triangular distance GEMM (diag last) + mirror + block minima
    gemm_mma<<<NTRI, 256, GEMM_SMEM>>>();

    topk_mixup_kernel<<<N0 / 8, 256>>>();
    topk_knn_kernel<<<NUM / 8, 256>>>();

    zero_stats_kernel<<<(CLASSES * DD + 255) / 256, 256>>>();
    scatter_kernel<<<NUM, 128>>>();
    mu_kernel<<<CLASSES, 128>>>();
    gm_kernel<<<NUM / GMP, 128>>>();

    final_kernel<<<1, 256>>>(out);
}

// round 16
// speedup vs baseline: 1.4336x; 1.1747x over previous
#include <cuda_runtime.h>
#include <cuda_bf16.h>
#include <cstdint>

#define N0      4096
#define NUM     8192
#define DD      512
#define KSP     1024          // 2-term split: A=[hi|lo](-2x)  B=[hi|hi](x)
#define CLASSES 100
#define NCH     16            // 1024 / 64
#define STAGE_BYTES 32768     // 16KB A + 16KB B
#define GEMM_SMEM (2 * STAGE_BYTES)
#define NBLK    256           // 32-col blocks per row
#define NTRI    2080          // 2016 strict-lower + 64 diagonal

// ---- device scratch ----
__device__ float g_x2[(size_t)NUM * DD];
__device__ float g_bb[NUM];
__device__ float g_y2[NUM];
__device__ float g_S[(size_t)NUM * NUM];            // only lower-triangle tiles written
__device__ float g_BM[(size_t)NUM * NBLK];          // per-32-col block minima (full)
__device__ __nv_bfloat16 g_A2[(size_t)NUM * KSP];
__device__ __nv_bfloat16 g_B2[(size_t)NUM * KSP];
__device__ float g_musum[CLASSES * DD];
__device__ float g_cnt[CLASSES];
__device__ float g_mu[CLASSES * DD];
__device__ float g_mumu[CLASSES];
__device__ float g_ptgm[NUM];
__device__ float g_ptknn[NUM];

__device__ __forceinline__ uint32_t smem_u32(const void* p) {
    uint32_t a;
    asm("{ .reg .u64 t; cvta.to.shared.u64 t, %1; cvt.u32.u64 %0, t; }" : "=r"(a) : "l"(p));
    return a;
}
__device__ __forceinline__ void cp16(uint32_t dst, const void* src) {
    asm volatile("cp.async.cg.shared.global [%0], [%1], 16;" :: "r"(dst), "l"(src));
}
__device__ __forceinline__ void ldm_x4(uint32_t addr, uint32_t& d0, uint32_t& d1,
                                       uint32_t& d2, uint32_t& d3) {
    asm volatile("ldmatrix.sync.aligned.m8n8.x4.shared.b16 {%0,%1,%2,%3}, [%4];"
                 : "=r"(d0), "=r"(d1), "=r"(d2), "=r"(d3) : "r"(addr));
}
__device__ __forceinline__ void mma_bf16(float* c, const uint32_t* a, uint32_t b0, uint32_t b1) {
    asm volatile("mma.sync.aligned.m16n8k16.row.col.f32.bf16.bf16.f32 "
                 "{%0,%1,%2,%3},{%4,%5,%6,%7},{%8,%9},{%0,%1,%2,%3};"
                 : "+f"(c[0]), "+f"(c[1]), "+f"(c[2]), "+f"(c[3])
                 : "r"(a[0]), "r"(a[1]), "r"(a[2]), "r"(a[3]), "r"(b0), "r"(b1));
}
__device__ __forceinline__ uint32_t pk(__nv_bfloat16 a, __nv_bfloat16 b) {
    union { __nv_bfloat162 h; uint32_t u; } t;
    t.h = __nv_bfloat162(a, b);
    return t.u;
}

// ---------------------------------------------------------------
// build: x2, bb, y lower half, and 2-term bf16 split operands
// ---------------------------------------------------------------
__global__ void build_kernel(const float* __restrict__ x, const float* __restrict__ y,
                             const float* __restrict__ lamp, const int* __restrict__ perm) {
    int row = blockIdx.x;
    int tid = threadIdx.x;
    float4 v;
    if (row < N0) {
        v = ((const float4*)(x + (size_t)row * DD))[tid];
        if (tid == 0) g_y2[row] = y[row];
    } else {
        int j = row - N0;
        float lam = *lamp, oml = 1.f - lam;
        int p = perm[j];
        float4 va = ((const float4*)(x + (size_t)j * DD))[tid];
        float4 vb = ((const float4*)(x + (size_t)p * DD))[tid];
        v.x = va.x * lam + vb.x * oml;
        v.y = va.y * lam + vb.y * oml;
        v.z = va.z * lam + vb.z * oml;
        v.w = va.w * lam + vb.w * oml;
    }
    ((float4*)(g_x2 + (size_t)row * DD))[tid] = v;
    float ss = v.x * v.x + v.y * v.y + v.z * v.z + v.w * v.w;

    float f[4] = {v.x, v.y, v.z, v.w};
    __nv_bfloat16* A = g_A2 + (size_t)row * KSP;
    __nv_bfloat16* B = g_B2 + (size_t)row * KSP;
    #pragma unroll
    for (int e = 0; e < 4; e += 2) {
        int d = tid * 4 + e;
        __nv_bfloat16 hb0, ha0, la0, hb1, ha1, la1;
        {
            float fb = f[e];
            hb0 = __float2bfloat16(fb);
            float fa = -2.f * fb;
            ha0 = __float2bfloat16(fa);
            la0 = __float2bfloat16(fa - __bfloat162float(ha0));
        }
        {
            float fb = f[e + 1];
            hb1 = __float2bfloat16(fb);
            float fa = -2.f * fb;
            ha1 = __float2bfloat16(fa);
            la1 = __float2bfloat16(fa - __bfloat162float(ha1));
        }
        *(uint32_t*)(A + d)       = pk(ha0, ha1);
        *(uint32_t*)(A + d + 512) = pk(la0, la1);
        *(uint32_t*)(B + d)       = pk(hb0, hb1);
        *(uint32_t*)(B + d + 512) = pk(hb0, hb1);
    }

    __shared__ float red[128];
    red[tid] = ss;
    __syncthreads();
    #pragma unroll
    for (int s = 64; s > 0; s >>= 1) {
        if (tid < s) red[tid] += red[tid + s];
        __syncthreads();
    }
    if (tid == 0) g_bb[row] = red[0];
}

// ---------------------------------------------------------------
// mma.sync distance GEMM, triangular grid. Lower tiles: write S + BM.
// Mirrored side: write BM ONLY (column-min from registers), no S store.
// CTA 128x128, 8 warps (2x4), warp tile 64x32, BK=64, 2-stage cp.async
// ---------------------------------------------------------------
__global__ __launch_bounds__(256, 2) void gemm_mma() {
    int b = blockIdx.x;
    int by, bx;
    if (b < 2016) {
        by = (int)((1.f + sqrtf(8.f * (float)b + 1.f)) * 0.5f);
        while (by * (by - 1) / 2 > b) by--;
        while ((by + 1) * by / 2 <= b) by++;
        bx = b - by * (by - 1) / 2;
    } else {
        by = bx = b - 2016;
    }

    extern __shared__ char smem[];
    const int tid  = threadIdx.x;
    const int lane = tid & 31;
    const int w    = tid >> 5;
    const int wm   = w >> 2, wn = w & 3;
    const uint32_t sbase = smem_u32(smem);

    const char* gA = (const char*)(g_A2 + (size_t)(by * 128) * KSP);
    const char* gB = (const char*)(g_B2 + (size_t)(bx * 128) * KSP);

    const int lrow = tid >> 3;
    const int lseg = tid & 7;

    float acc[4][4][4];
    #pragma unroll
    for (int mt = 0; mt < 4; mt++)
        #pragma unroll
        for (int nt = 0; nt < 4; nt++)
            #pragma unroll
            for (int e = 0; e < 4; e++) acc[mt][nt][e] = 0.f;

    #define ISSUE(chunk, stg)                                                        \
    {                                                                                \
        uint32_t sA = sbase + (stg) * STAGE_BYTES;                                   \
        uint32_t sB = sA + 16384;                                                    \
        _Pragma("unroll")                                                            \
        for (int r = 0; r < 4; r++) {                                                \
            int row = lrow + r * 32;                                                 \
            uint32_t d = (uint32_t)(row * 128 + ((lseg ^ (row & 7)) * 16));          \
            cp16(sA + d, gA + (size_t)row * (KSP * 2) + (chunk) * 128 + lseg * 16);  \
            cp16(sB + d, gB + (size_t)row * (KSP * 2) + (chunk) * 128 + lseg * 16);  \
        }                                                                            \
        asm volatile("cp.async.commit_group;" ::: "memory");                         \
    }

    ISSUE(0, 0);
    for (int i = 0; i < NCH; i++) {
        const int stg = i & 1;
        if (i + 1 < NCH) {
            ISSUE(i + 1, stg ^ 1);
            asm volatile("cp.async.wait_group 1;" ::: "memory");
        } else {
            asm volatile("cp.async.wait_group 0;" ::: "memory");
        }
        __syncthreads();

        const uint32_t sA = sbase + stg * STAGE_BYTES;
        const uint32_t sB = sA + 16384;
        #pragma unroll
        for (int kk = 0; kk < 4; kk++) {
            const int half = lane >> 4;
            uint32_t a[4][4];
            #pragma unroll
            for (int mt = 0; mt < 4; mt++) {
                int row = wm * 64 + mt * 16 + (lane & 15);
                uint32_t ad = sA + row * 128 + (((kk * 2 + half) ^ (row & 7)) * 16);
                ldm_x4(ad, a[mt][0], a[mt][1], a[mt][2], a[mt][3]);
            }
            uint32_t bfr[2][4];
            #pragma unroll
            for (int pt = 0; pt < 2; pt++) {
                int nrow = wn * 32 + pt * 16 + ((lane >> 3) & 1) * 8 + (lane & 7);
                uint32_t bd = sB + nrow * 128 + (((kk * 2 + half) ^ (nrow & 7)) * 16);
                ldm_x4(bd, bfr[pt][0], bfr[pt][1], bfr[pt][2], bfr[pt][3]);
            }
            #pragma unroll
            for (int mt = 0; mt < 4; mt++)
                #pragma unroll
                for (int nt = 0; nt < 4; nt++) {
                    int pt = nt >> 1, sub = nt & 1;
                    mma_bf16(acc[mt][nt], a[mt], bfr[pt][sub], bfr[pt][sub + 2]);
                }
        }
        __syncthreads();
    }
    #undef ISSUE

    const int mb0 = by * 128, nb0 = bx * 128;
    const int r0 = lane >> 2;
    const int c0 = (lane & 3) * 2;

    // ---- straight tile: S + 32-col block minima ----
    {
        float bbv[4][2];
        #pragma unroll
        for (int nt = 0; nt < 4; nt++) {
            int col = nb0 + wn * 32 + nt * 8 + c0;
            bbv[nt][0] = g_bb[col];
            bbv[nt][1] = g_bb[col + 1];
        }
        #pragma unroll
        for (int mt = 0; mt < 4; mt++) {
            int m0 = mb0 + wm * 64 + mt * 16 + r0;
            float rmin0 = INFINITY, rmin1 = INFINITY;
            #pragma unroll
            for (int nt = 0; nt < 4; nt++) {
                int col = nb0 + wn * 32 + nt * 8 + c0;
                float2 v0, v1;
                v0.x = bbv[nt][0] + acc[mt][nt][0];
                v0.y = bbv[nt][1] + acc[mt][nt][1];
                v1.x = bbv[nt][0] + acc[mt][nt][2];
                v1.y = bbv[nt][1] + acc[mt][nt][3];
                *(float2*)&g_S[(size_t)m0 * NUM + col]       = v0;
                *(float2*)&g_S[(size_t)(m0 + 8) * NUM + col] = v1;
                rmin0 = fminf(rmin0, fminf(v0.x, v0.y));
                rmin1 = fminf(rmin1, fminf(v1.x, v1.y));
            }
            rmin0 = fminf(rmin0, __shfl_xor_sync(0xffffffffu, rmin0, 1));
            rmin0 = fminf(rmin0, __shfl_xor_sync(0xffffffffu, rmin0, 2));
            rmin1 = fminf(rmin1, __shfl_xor_sync(0xffffffffu, rmin1, 1));
            rmin1 = fminf(rmin1, __shfl_xor_sync(0xffffffffu, rmin1, 2));
            if ((lane & 3) == 0) {
                int blk = (nb0 >> 5) + wn;
                g_BM[(size_t)m0 * NBLK + blk]       = rmin0;
                g_BM[(size_t)(m0 + 8) * NBLK + blk] = rmin1;
            }
        }
    }

    // ---- mirrored side (off-diagonal): BM only, from register column-mins ----
    if (bx != by) {
        float bbr[4][2];
        #pragma unroll
        for (int mt = 0; mt < 4; mt++) {
            int m0 = mb0 + wm * 64 + mt * 16 + r0;
            bbr[mt][0] = g_bb[m0];
            bbr[mt][1] = g_bb[m0 + 8];
        }
        float* colmin = (float*)smem;    // [128 cols][4 m-blocks] = 2KB
        #pragma unroll
        for (int nt = 0; nt < 4; nt++) {
            // per column pair (c0, c0+1): mins over m-groups {mt 0,1} and {mt 2,3}
            float g0c0 = INFINITY, g1c0 = INFINITY, g0c1 = INFINITY, g1c1 = INFINITY;
            #pragma unroll
            for (int mt = 0; mt < 2; mt++) {
                g0c0 = fminf(g0c0, fminf(acc[mt][nt][0] + bbr[mt][0], acc[mt][nt][2] + bbr[mt][1]));
                g0c1 = fminf(g0c1, fminf(acc[mt][nt][1] + bbr[mt][0], acc[mt][nt][3] + bbr[mt][1]));
            }
            #pragma unroll
            for (int mt = 2; mt < 4; mt++) {
                g1c0 = fminf(g1c0, fminf(acc[mt][nt][0] + bbr[mt][0], acc[mt][nt][2] + bbr[mt][1]));
                g1c1 = fminf(g1c1, fminf(acc[mt][nt][1] + bbr[mt][0], acc[mt][nt][3] + bbr[mt][1]));
            }
            // reduce over r0 (8 lanes apart at stride 4)
            #pragma unroll
            for (int o = 4; o <= 16; o <<= 1) {
                g0c0 = fminf(g0c0, __shfl_xor_sync(0xffffffffu, g0c0, o));
                g1c0 = fminf(g1c0, __shfl_xor_sync(0xffffffffu, g1c0, o));
                g0c1 = fminf(g0c1, __shfl_xor_sync(0xffffffffu, g0c1, o));
                g1c1 = fminf(g1c1, __shfl_xor_sync(0xffffffffu, g1c1, o));
            }
            if (lane < 4) {
                int cl = wn * 32 + nt * 8 + c0;
                colmin[cl * 4 + wm * 2]           = g0c0;
                colmin[cl * 4 + wm * 2 + 1]       = g1c0;
                colmin[(cl + 1) * 4 + wm * 2]     = g0c1;
                colmin[(cl + 1) * 4 + wm * 2 + 1] = g1c1;
            }
        }
        __syncthreads();
        if (tid < 128) {
            float4 cm = ((float4*)colmin)[tid];
            *(float4*)&g_BM[(size_t)(nb0 + tid) * NBLK + (mb0 >> 5)] = cm;
        }
    }
}

// ---------------------------------------------------------------
// top-K helpers (exact jax tie-break)
// ---------------------------------------------------------------
template <int K>
__device__ __forceinline__ void ins(float* v, int* ix, float s, int j) {
    bool better = (s < v[K - 1]) || (s == v[K - 1] && j < ix[K - 1]);
    if (better) {
        v[K - 1] = s; ix[K - 1] = j;
        #pragma unroll
        for (int t = K - 1; t > 0; t--) {
            bool sw = (v[t] < v[t - 1]) || (v[t] == v[t - 1] && ix[t] < ix[t - 1]);
            float tv = sw ? v[t - 1] : v[t];
            float bv = sw ? v[t] : v[t - 1];
            int   ti = sw ? ix[t - 1] : ix[t];
            int   bi = sw ? ix[t] : ix[t - 1];
            v[t] = tv; v[t - 1] = bv; ix[t] = ti; ix[t - 1] = bi;
        }
    }
}

template <int K>
__device__ __forceinline__ void warp_popk(float* v, int* ix, float* out_v, int* out_i) {
    #pragma unroll
    for (int r = 0; r < K; r++) {
        float bv = v[0]; int bi = ix[0];
        #pragma unroll
        for (int o = 16; o > 0; o >>= 1) {
            float ov = __shfl_xor_sync(0xffffffffu, bv, o);
            int   oi = __shfl_xor_sync(0xffffffffu, bi, o);
            if (ov < bv || (ov == bv && oi < bi)) { bv = ov; bi = oi; }
        }
        out_v[r] = bv; out_i[r] = bi;
        if (bv == v[0] && bi == ix[0]) {
            #pragma unroll
            for (int t = 0; t < K - 1; t++) { v[t] = v[t + 1]; ix[t] = ix[t + 1]; }
            v[K - 1] = INFINITY; ix[K - 1] = 0x7fffffff;
        }
    }
}

template <int K>
__device__ __forceinline__ float mode_k(const float* lab) {
    float best = 0.f; int bc = -1;
    #pragma unroll
    for (int a = 0; a < K; a++) {
        int c = 0;
        #pragma unroll
        for (int b = 0; b < K; b++) c += (lab[a] == lab[b]);
        if (c > bc || (c == bc && lab[a] < best)) { bc = c; best = lab[a]; }
    }
    return best;
}

// mixup: rows 4096.. always lower-triangle vs cols <4096 -> straight reads only
__global__ void topk_mixup_kernel() {
    int warp = (blockIdx.x * blockDim.x + threadIdx.x) >> 5;
    int lane = threadIdx.x & 31;
    if (warp >= N0) return;
    const float* Srow = g_S + (size_t)(N0 + warp) * NUM;
    const float* BMrow = g_BM + (size_t)(N0 + warp) * NBLK;
    float4 bm4 = *(const float4*)(BMrow + lane * 4);
    float bmv[4] = {bm4.x, bm4.y, bm4.z, bm4.w};

    float v[11]; int ix[11];
    #pragma unroll
    for (int t = 0; t < 11; t++) { v[t] = INFINITY; ix[t] = 0x7fffffff; }
    #pragma unroll
    for (int e = 0; e < 4; e++) ins<11>(v, ix, bmv[e], lane * 4 + e);
    float tv[11]; int ti[11];
    warp_popk<11>(v, ix, tv, ti);
    float T = tv[10];

    #pragma unroll
    for (int t = 0; t < 11; t++) { v[t] = INFINITY; ix[t] = 0x7fffffff; }
    #pragma unroll
    for (int e = 0; e < 4; e++) {
        unsigned m = __ballot_sync(0xffffffffu, bmv[e] <= T);
        while (m) {
            int L = __ffs(m) - 1; m &= m - 1;
            int bk = L * 4 + e;
            int j = bk * 32 + lane;
            ins<11>(v, ix, Srow[j], j);
        }
    }
    warp_popk<11>(v, ix, tv, ti);
    if (lane == 0) {
        float lab[11];
        #pragma unroll
        for (int t = 0; t < 11; t++) lab[t] = g_y2[ti[t]];
        g_y2[N0 + warp] = mode_k<11>(lab);
    }
}

// knn: candidate blocks above the diagonal reconstruct from transposed S
__global__ void topk_knn_kernel() {
    int warp = (blockIdx.x * blockDim.x + threadIdx.x) >> 5;
    int lane = threadIdx.x & 31;
    if (warp >= NUM) return;
    const float* Srow = g_S + (size_t)warp * NUM;
    const float* BMrow = g_BM + (size_t)warp * NBLK;
    float4 a0 = *(const float4*)(BMrow + lane * 8);
    float4 a1 = *(const float4*)(BMrow + lane * 8 + 4);
    float bmv[8] = {a0.x, a0.y, a0.z, a0.w, a1.x, a1.y, a1.z, a1.w};
    const int rtile = warp >> 7;
    const float bbr = g_bb[warp];

    float v[4]; int ix[4];
    #pragma unroll
    for (int t = 0; t < 4; t++) { v[t] = INFINITY; ix[t] = 0x7fffffff; }
    #pragma unroll
    for (int e = 0; e < 8; e++) ins<4>(v, ix, bmv[e], lane * 8 + e);
    float tv[4]; int ti[4];
    warp_popk<4>(v, ix, tv, ti);
    float T = tv[3];

    #pragma unroll
    for (int t = 0; t < 4; t++) { v[t] = INFINITY; ix[t] = 0x7fffffff; }
    #pragma unroll
    for (int e = 0; e < 8; e++) {
        unsigned m = __ballot_sync(0xffffffffu, bmv[e] <= T);
        while (m) {
            int L = __ffs(m) - 1; m &= m - 1;
            int bk = L * 8 + e;
            int j = bk * 32 + lane;
            float s;
            if ((bk >> 2) <= rtile) {
                s = Srow[j];                                   // stored straight
            } else {                                           // reconstruct from S[j][warp]
                s = g_S[(size_t)j * NUM + warp] + (g_bb[j] - bbr);
            }
            ins<4>(v, ix, s, j);
        }
    }
    warp_popk<4>(v, ix, tv, ti);
    if (lane == 0) {
        float lab[3];
        lab[0] = g_y2[ti[1]]; lab[1] = g_y2[ti[2]]; lab[2] = g_y2[ti[3]];
        float m = mode_k<3>(lab);
        float d = m - g_y2[warp];
        g_ptknn[warp] = d * d;
    }
}

// ---------------------------------------------------------------
// class statistics + gm loss + final reduce
// ---------------------------------------------------------------
__global__ void zero_stats_kernel() {
    int i = blockIdx.x * blockDim.x + threadIdx.x;
    if (i < CLASSES * DD) g_musum[i] = 0.f;
    if (i < CLASSES)      g_cnt[i]   = 0.f;
}

__global__ void scatter_kernel() {
    int i = blockIdx.x;
    int tid = threadIdx.x;
    int c = (int)g_y2[i];
    const float* xr = g_x2 + (size_t)i * DD;
    for (int d = tid; d < DD; d += 128)
        atomicAdd(&g_musum[c * DD + d], xr[d]);
    if (tid == 0) atomicAdd(&g_cnt[c], 1.f);
}

__global__ void mu_kernel() {
    int c = blockIdx.x, tid = threadIdx.x;
    float inv = 1.f / fmaxf(g_cnt[c], 1.f);
    float ss = 0.f;
    for (int d = tid; d < DD; d += 128) {
        float m = g_musum[c * DD + d] * inv;
        g_mu[c * DD + d] = m;
        ss += m * m;
    }
    __shared__ float red[128];
    red[tid] = ss;
    __syncthreads();
    #pragma unroll
    for (int s = 64; s > 0; s >>= 1) {
        if (tid < s) red[tid] += red[tid + s];
        __syncthreads();
    }
    if (tid == 0) g_mumu[c] = red[0];
}

// 16 points per block; 50 threads x 2 classes
#define GMP 16
__global__ void gm_kernel() {
    int i0 = blockIdx.x * GMP, tid = threadIdx.x;
    int wid = tid >> 5, lane = tid & 31;
    __shared__ float xs[GMP][DD];
    for (int t = tid; t < GMP * DD / 4; t += 128) {
        int p = t / (DD / 4), k = t % (DD / 4);
        ((float4*)xs[p])[k] = ((const float4*)(g_x2 + (size_t)(i0 + p) * DD))[k];
    }
    __syncthreads();

    float w0[GMP], w1[GMP];
    #pragma unroll
    for (int p = 0; p < GMP; p++) { w0[p] = 0.f; w1[p] = 0.f; }
    int c1 = tid, c2 = tid + 50;
    if (tid < 50) {
        const float4* mua = (const float4*)(g_mu + c1 * DD);
        const float4* mub = (const float4*)(g_mu + c2 * DD);
        float d0[GMP], d1[GMP];
        #pragma unroll
        for (int p = 0; p < GMP; p++) { d0[p] = 0.f; d1[p] = 0.f; }
        for (int k = 0; k < DD / 4; k++) {
            float4 ba = mua[k];
            float4 bb4 = mub[k];
            #pragma unroll
            for (int p = 0; p < GMP; p++) {
                float4 a = ((const float4*)xs[p])[k];
                d0[p] = fmaf(a.x, ba.x, d0[p]);
                d0[p] = fmaf(a.y, ba.y, d0[p]);
                d0[p] = fmaf(a.z, ba.z, d0[p]);
                d0[p] = fmaf(a.w, ba.w, d0[p]);
                d1[p] = fmaf(a.x, bb4.x, d1[p]);
                d1[p] = fmaf(a.y, bb4.y, d1[p]);
                d1[p] = fmaf(a.z, bb4.z, d1[p]);
                d1[p] = fmaf(a.w, bb4.w, d1[p]);
            }
        }
        float l0 = (g_cnt[c1] > 0.f) ? 1.f : 0.f;
        float l1 = (g_cnt[c2] > 0.f) ? 1.f : 0.f;
        float mm0 = g_mumu[c1], mm1 = g_mumu[c2];
        #pragma unroll
        for (int p = 0; p < GMP; p++) {
            float bbp = g_bb[i0 + p];
            w0[p] = l0 * expf(-0.5f * (bbp + mm0 - 2.f * d0[p]));
            w1[p] = l1 * expf(-0.5f * (bbp + mm1 - 2.f * d1[p]));
        }
    }
    __shared__ float wred[4], tred[4];
    for (int p = 0; p < GMP; p++) {
        float s = w0[p] + w1[p];
        #pragma unroll
        for (int o = 16; o > 0; o >>= 1) s += __shfl_xor_sync(0xffffffffu, s, o);
        if (lane == 0) wred[wid] = s;
        __syncthreads();
        float wsum = wred[0] + wred[1] + wred[2] + wred[3];
        float t = 0.f;
        if (tid < 50) {
            int yi = (int)g_y2[i0 + p];
            float pp0 = fminf(fmaxf(w0[p] / (wsum + 1e-15f), 0.f), 1.f);
            float dd0 = pp0 - ((c1 == yi) ? 1.f : 0.f);
            float pp1 = fminf(fmaxf(w1[p] / (wsum + 1e-15f), 0.f), 1.f);
            float dd1 = pp1 - ((c2 == yi) ? 1.f : 0.f);
            t = dd0 * dd0 + dd1 * dd1;
        }
        #pragma unroll
        for (int o = 16; o > 0; o >>= 1) t += __shfl_xor_sync(0xffffffffu, t, o);
        if (lane == 0) tred[wid] = t;
        __syncthreads();
        if (tid == 0) g_ptgm[i0 + p] = tred[0] + tred[1] + tred[2] + tred[3];
        __syncthreads();
    }
}

__global__ void final_kernel(float* __restrict__ out) {
    __shared__ float red[256];
    int tid = threadIdx.x;
    float s1 = 0.f, s2 = 0.f;
    for (int i = tid; i < NUM; i += 256) { s1 += g_ptgm[i]; s2 += g_ptknn[i]; }
    red[tid] = s1;
    __syncthreads();
    #pragma unroll
    for (int s = 128; s > 0; s >>= 1) {
        if (tid < s) red[tid] += red[tid + s];
        __syncthreads();
    }
    float t1 = red[0];
    __syncthreads();
    red[tid] = s2;
    __syncthreads();
    #pragma unroll
    for (int s = 128; s > 0; s >>= 1) {
        if (tid < s) red[tid] += red[tid + s];
        __syncthreads();
    }
    if (tid == 0) out[0] = t1 / (float)NUM + 0.01f * red[0] / (float)NUM;
}

// ---------------------------------------------------------------
extern "C" void kernel_launch(void* const* d_in, const int* in_sizes, int n_in,
                              void* d_out, int out_size) {
    const float* x    = (const float*)d_in[0];
    const float* y    = (const float*)d_in[1];
    const float* lam  = (const float*)d_in[2];
    const int*   perm = (const int*)d_in[3];
    float* out = (float*)d_out;

    cudaFuncSetAttribute(gemm_mma, cudaFuncAttributeMaxDynamicSharedMemorySize, GEMM_SMEM);

    build_kernel<<<NUM, 128>>>(x, y, lam, perm);

    // triangular distance GEMM: straight S + full BM (mirror side BM-only)
    gemm_mma<<<NTRI, 256, GEMM_SMEM>>>();

    topk_mixup_kernel<<<N0 / 8, 256>>>();
    topk_knn_kernel<<<NUM / 8, 256>>>();

    zero_stats_kernel<<<(CLASSES * DD + 255) / 256, 256>>>();
    scatter_kernel<<<NUM, 128>>>();
    mu_kernel<<<CLASSES, 128>>>();
    gm_kernel<<<NUM / GMP, 128>>>();

    final_kernel<<<1, 256>>>(out);
}